// round 12
// baseline (speedup 1.0000x reference)
#include <cuda_runtime.h>
#include <cstdint>

#define KK 4096
#define NPIX (64*32*256)
#define POSINF __int_as_float(0x7f800000)

__device__ float g_zrest[NPIX];
__device__ float g_wsq[KK];
__device__ float g_pd[32768];
__device__ int   g_pi[32768];

typedef unsigned long long ull;

// ---------- level 0: wsq + downsample + full-codebook dist (per batch) ------
__global__ void __launch_bounds__(256) k_dist0(const float* __restrict__ z,
                                               const float* __restrict__ emb) {
    __shared__ float zds[32];
    __shared__ float zqs;
    __shared__ float pdw[8];
    __shared__ int   piw[8];
    int b = blockIdx.x, tid = threadIdx.x;
    int wid = tid >> 5, lane = tid & 31;

    if (tid < 32) {
        const float* base = z + (b * 32 + tid) * 256;
        float s = 0.f;
        for (int i = 0; i < 256; i++) s = __fadd_rn(s, base[i]);
        float zd = __fmul_rn(s, 1.f / 256.f);
        zds[tid] = zd;
        float q = __fmul_rn(zd, zd);
#pragma unroll
        for (int off = 16; off; off >>= 1)
            q = __fadd_rn(q, __shfl_xor_sync(0xffffffffu, q, off));
        if (tid == 0) zqs = q;
    }
    __syncthreads();

    float zr[32];
#pragma unroll
    for (int c = 0; c < 32; c++) zr[c] = zds[c];
    float zq = zqs;

    float bd = POSINF; int bk = 0;
    for (int kk = 0; kk < 16; kk++) {
        int k = tid * 16 + kk;
        const float4* e4 = (const float4*)(emb + k * 32);
        float ws = 0.f, dot = 0.f;
#pragma unroll
        for (int s8 = 0; s8 < 8; s8++) {
            float4 w4 = e4[s8];
            ws = __fadd_rn(ws, __fmul_rn(w4.x, w4.x)); dot = __fmaf_rn(zr[s8*4+0], w4.x, dot);
            ws = __fadd_rn(ws, __fmul_rn(w4.y, w4.y)); dot = __fmaf_rn(zr[s8*4+1], w4.y, dot);
            ws = __fadd_rn(ws, __fmul_rn(w4.z, w4.z)); dot = __fmaf_rn(zr[s8*4+2], w4.z, dot);
            ws = __fadd_rn(ws, __fmul_rn(w4.w, w4.w)); dot = __fmaf_rn(zr[s8*4+3], w4.w, dot);
        }
        if (b == 0) g_wsq[k] = ws;
        float d = __fadd_rn(__fadd_rn(zq, ws), __fmul_rn(-2.f, dot));
        if (d < bd) { bd = d; bk = k; }
    }
#pragma unroll
    for (int off = 16; off; off >>= 1) {
        float od = __shfl_xor_sync(0xffffffffu, bd, off);
        int   ok = __shfl_xor_sync(0xffffffffu, bk, off);
        if (od < bd || (od == bd && ok < bk)) { bd = od; bk = ok; }
    }
    if (lane == 0) { pdw[wid] = bd; piw[wid] = bk; }
    __syncthreads();
    if (tid == 0) {
        float bdv = pdw[0]; int bkv = piw[0];
        for (int wd = 1; wd < 8; wd++)
            if (pdw[wd] < bdv || (pdw[wd] == bdv && piw[wd] < bkv)) { bdv = pdw[wd]; bkv = piw[wd]; }
        g_pd[b] = bdv; g_pi[b] = bkv;
    }
}

// ---------- dist+argmin (L1-L4): in-CTA downsample + pipelined f32x2 --------
// 64 tok x 128 codes per iter; lp = log2(pn), sub = 16>>lp.
__global__ void __launch_bounds__(256, 2) k_dist(const float* __restrict__ emb,
                                                 int cps, int iters, int lp) {
    __shared__ float zs[32][64];
    __shared__ ulonglong2 es2[4][32][16];
    __shared__ float ws[128];
    int tid = threadIdx.x;
    int tx = tid & 15, ty = tid >> 4;
    int tb = blockIdx.x * 64;
    int pn = 1 << lp, sub = 16 >> lp;
    float inv = 1.f / (float)(sub * sub);

    // in-CTA downsample: 64 tok x 32 ch = 2048 pairs, 8/thread
    for (int s = tid; s < 2048; s += 256) {
        int tok = s >> 5, c = s & 31;
        int g = tb + tok;
        int batch = g >> (2 * lp);
        int rem = g & (pn * pn - 1);
        int yy = rem >> lp, xx = rem & (pn - 1);
        const float* base = g_zrest + ((batch * 32 + c) * 16 + yy * sub) * 16 + xx * sub;
        float acc = 0.f;
        for (int dy = 0; dy < sub; dy++)
            for (int dx = 0; dx < sub; dx++)
                acc = __fadd_rn(acc, base[dy * 16 + dx]);
        zs[c][tok] = __fmul_rn(acc, inv);
    }
    __syncthreads();

    // zq per thread for its 4 tokens (sequential over channels)
    float zq[4];
#pragma unroll
    for (int j = 0; j < 4; j++) {
        int tok = ty * 4 + j;
        float q = 0.f;
#pragma unroll
        for (int c = 0; c < 32; c++) {
            float v = zs[c][tok];
            q = __fadd_rn(q, __fmul_rn(v, v));
        }
        zq[j] = q;
    }

    float bd[4]; int bk[4];
#pragma unroll
    for (int j = 0; j < 4; j++) { bd[j] = POSINF; bk[j] = 0; }

    int kbase = blockIdx.y * cps;
    for (int it = 0; it < iters; it++) {
        int kb = kbase + it * 128;
        __syncthreads();
        {
            int pair = tid >> 2, part = tid & 3;
            int txi = pair & 15, h = pair >> 4;
            int c0 = part * 8;
            int code0 = kb + txi * 8 + 2 * h;
            const float4* p0 = (const float4*)(emb + code0 * 32 + part * 8);
            const float4* p1 = (const float4*)(emb + (code0 + 1) * 32 + part * 8);
            float4 a0 = p0[0], a1 = p0[1];
            float4 b0 = p1[0], b1 = p1[1];
            float e0[8] = {a0.x,a0.y,a0.z,a0.w,a1.x,a1.y,a1.z,a1.w};
            float e1[8] = {b0.x,b0.y,b0.z,b0.w,b1.x,b1.y,b1.z,b1.w};
#pragma unroll
            for (int i = 0; i < 8; i++) {
                ull d0, d1;
                asm("mov.b64 %0, {%1, %1};" : "=l"(d0) : "f"(e0[i]));
                asm("mov.b64 %0, {%1, %1};" : "=l"(d1) : "f"(e1[i]));
                es2[h][c0 + i][txi] = make_ulonglong2(d0, d1);
            }
        }
        if (tid < 128) ws[tid] = g_wsq[kb + tid];
        __syncthreads();

        ull acc[2][8];
#pragma unroll
        for (int p = 0; p < 2; p++)
#pragma unroll
            for (int k = 0; k < 8; k++) acc[p][k] = 0ull;

        ull zp[2], ed[8];
        {
            ulonglong2 zp2 = *(const ulonglong2*)&zs[0][ty * 4];
            zp[0] = zp2.x; zp[1] = zp2.y;
            ulonglong2 e0 = es2[0][0][tx], e1 = es2[1][0][tx];
            ulonglong2 e2 = es2[2][0][tx], e3 = es2[3][0][tx];
            ed[0]=e0.x; ed[1]=e0.y; ed[2]=e1.x; ed[3]=e1.y;
            ed[4]=e2.x; ed[5]=e2.y; ed[6]=e3.x; ed[7]=e3.y;
        }
#pragma unroll
        for (int c = 0; c < 32; c++) {
            ull zpn[2], edn[8];
            if (c < 31) {
                ulonglong2 zp2 = *(const ulonglong2*)&zs[c + 1][ty * 4];
                zpn[0] = zp2.x; zpn[1] = zp2.y;
                ulonglong2 e0 = es2[0][c + 1][tx], e1 = es2[1][c + 1][tx];
                ulonglong2 e2 = es2[2][c + 1][tx], e3 = es2[3][c + 1][tx];
                edn[0]=e0.x; edn[1]=e0.y; edn[2]=e1.x; edn[3]=e1.y;
                edn[4]=e2.x; edn[5]=e2.y; edn[6]=e3.x; edn[7]=e3.y;
            }
#pragma unroll
            for (int p = 0; p < 2; p++)
#pragma unroll
                for (int k = 0; k < 8; k++)
                    asm("fma.rn.f32x2 %0, %1, %2, %0;"
                        : "+l"(acc[p][k]) : "l"(zp[p]), "l"(ed[k]));
            if (c < 31) {
                zp[0] = zpn[0]; zp[1] = zpn[1];
#pragma unroll
                for (int i = 0; i < 8; i++) ed[i] = edn[i];
            }
        }

#pragma unroll
        for (int p = 0; p < 2; p++) {
#pragma unroll
            for (int k = 0; k < 8; k++) {
                float lo, hi;
                asm("mov.b64 {%0, %1}, %2;" : "=f"(lo), "=f"(hi) : "l"(acc[p][k]));
                int kk = kb + tx * 8 + k;
                float wv = ws[tx * 8 + k];
                float d0 = __fadd_rn(__fadd_rn(zq[2*p],   wv), __fmul_rn(-2.f, lo));
                float d1 = __fadd_rn(__fadd_rn(zq[2*p+1], wv), __fmul_rn(-2.f, hi));
                if (d0 < bd[2*p])   { bd[2*p]   = d0; bk[2*p]   = kk; }
                if (d1 < bd[2*p+1]) { bd[2*p+1] = d1; bk[2*p+1] = kk; }
            }
        }
    }

#pragma unroll
    for (int j = 0; j < 4; j++) {
        float d = bd[j]; int k = bk[j];
#pragma unroll
        for (int off = 8; off; off >>= 1) {
            float od = __shfl_xor_sync(0xffffffffu, d, off, 16);
            int   ok = __shfl_xor_sync(0xffffffffu, k, off, 16);
            if (od < d || (od == d && ok < k)) { d = od; k = ok; }
        }
        if (tx == 0) {
            int t = tb + ty * 4 + j;
            g_pd[t * gridDim.y + blockIdx.y] = d;
            g_pi[t * gridDim.y + blockIdx.y] = k;
        }
    }
}

// ---------- cubic (jax Keys a=-0.5) weights, renormalized ----------
template<int PN>
__device__ __forceinline__ void cubw(int o, float* w) {
    if (PN == 1) { w[0] = 1.f; return; }
    float s = __fadd_rn(__fmul_rn(__fadd_rn((float)o, 0.5f), (float)PN / 16.f), -0.5f);
    float tot = 0.f;
#pragma unroll
    for (int i = 0; i < PN; i++) {
        float x = fabsf(s - (float)i);
        float v;
        if (x >= 2.f)      v = 0.f;
        else if (x >= 1.f) v = ((-0.5f * x + 2.5f) * x - 4.f) * x + 2.f;
        else               v = ((1.5f * x - 2.5f) * x) * x + 1.f;
        w[i] = v; tot += v;
    }
#pragma unroll
    for (int i = 0; i < PN; i++) w[i] = w[i] / tot;
}

// ---------- pixel-split up: reduce + gather + bicubic + zrest (L0-L3) -------
// grid (64 batches, 4 row-quadrants); 256 thr = 64 pixels x 4 channel-groups.
template<int PN>
__global__ void __launch_bounds__(256) k_up(const float* __restrict__ emb,
                                            const float* __restrict__ outPrev,
                                            float* __restrict__ outCur,
                                            int isFirst, int KS,
                                            const float* __restrict__ z0) {
    constexpr int NT = PN * PN;
    __shared__ float pdp[256];
    __shared__ int   pip[256];
    __shared__ int   tok_s[NT];
    __shared__ float ew[NT][33];
    int b = blockIdx.x, tid = threadIdx.x;

    int tot = NT * KS;
    for (int i = tid; i < tot; i += 256) {
        pdp[i] = g_pd[b * tot + i];
        pip[i] = g_pi[b * tot + i];
    }
    __syncthreads();
    if (tid < NT) {
        float bdv = pdp[tid * KS]; int bkv = pip[tid * KS];
        for (int s = 1; s < KS; s++) {
            float d = pdp[tid * KS + s]; int k = pip[tid * KS + s];
            if (d < bdv || (d == bdv && k < bkv)) { bdv = d; bkv = k; }
        }
        tok_s[tid] = bkv;
    }
    __syncthreads();

    for (int idx = tid; idx < NT * 8; idx += 256) {
        int token = idx >> 3, seg = idx & 7;
        float4 v = *(const float4*)(emb + tok_s[token] * 32 + seg * 4);
        ew[token][seg*4+0] = v.x; ew[token][seg*4+1] = v.y;
        ew[token][seg*4+2] = v.z; ew[token][seg*4+3] = v.w;
    }
    __syncthreads();

    int pix = tid & 63, cg = tid >> 6;
    int r = (blockIdx.y << 2) + (pix >> 4), x = pix & 15;
    float wy[PN], wx[PN];
    cubw<PN>(r, wy);
    cubw<PN>(x, wx);
#pragma unroll
    for (int cc = 0; cc < 8; cc++) {
        int c = cg * 8 + cc;
        float acc = 0.f;
#pragma unroll
        for (int j = 0; j < PN; j++) {
            float tmp = 0.f;
#pragma unroll
            for (int i = 0; i < PN; i++) tmp += wx[i] * ew[j * PN + i][c];
            acc += wy[j] * tmp;
        }
        int idx = (b * 32 + c) * 256 + r * 16 + x;
        float prev = isFirst ? 0.f : outPrev[idx];
        outCur[idx] = prev + acc;
        float zin = isFirst ? z0[idx] : g_zrest[idx];
        g_zrest[idx] = zin - acc;
    }
}

// ---------- last level: reduce(KS=2) + gather + accumulate, pixel-split -----
__global__ void __launch_bounds__(256) k_up_last(const float* __restrict__ emb,
                                                 const float* __restrict__ outPrev,
                                                 float* __restrict__ outCur) {
    int b = blockIdx.x, tid = threadIdx.x;
    int pix = tid & 63, cg = tid >> 6;
    int r = (blockIdx.y << 2) + (pix >> 4), x = pix & 15;
    int t = b * 256 + r * 16 + x;
    float d0 = g_pd[t * 2], d1 = g_pd[t * 2 + 1];
    int   k0 = g_pi[t * 2], k1 = g_pi[t * 2 + 1];
    int tok = (d1 < d0 || (d1 == d0 && k1 < k0)) ? k1 : k0;
    const float4* e4 = (const float4*)(emb + tok * 32 + cg * 8);
    float4 ea = e4[0], eb = e4[1];
    float ev[8] = {ea.x, ea.y, ea.z, ea.w, eb.x, eb.y, eb.z, eb.w};
#pragma unroll
    for (int cc = 0; cc < 8; cc++) {
        int c = cg * 8 + cc;
        int idx = (b * 32 + c) * 256 + r * 16 + x;
        outCur[idx] = outPrev[idx] + ev[cc];
    }
}

extern "C" void kernel_launch(void* const* d_in, const int* in_sizes, int n_in,
                              void* d_out, int out_size) {
    const float* z = (const float*)d_in[0];
    const float* w = (const float*)d_in[1];
    float* out = (float*)d_out;
    float* o0 = out;
    float* o1 = out + (size_t)NPIX;
    float* o2 = out + 2 * (size_t)NPIX;
    float* o3 = out + 3 * (size_t)NPIX;
    float* o4 = out + 4 * (size_t)NPIX;
    dim3 gu(64, 4);

    // L0: 64 tokens, full codebook per block
    k_dist0<<<64, 256>>>(z, w);
    k_up<1><<<gu, 256>>>(w, o0, o0, 1, 1, z);

    // L1: 256 tokens, pn=2
    k_dist<<<dim3(4, 16), 256>>>(w, 256, 2, 1);
    k_up<2><<<gu, 256>>>(w, o0, o1, 0, 16, z);

    // L2: 1024 tokens, pn=4
    k_dist<<<dim3(16, 16), 256>>>(w, 256, 2, 2);
    k_up<4><<<gu, 256>>>(w, o1, o2, 0, 16, z);

    // L3: 4096 tokens, pn=8
    k_dist<<<dim3(64, 4), 256>>>(w, 1024, 8, 3);
    k_up<8><<<gu, 256>>>(w, o2, o3, 0, 4, z);

    // L4: 16384 tokens, pn=16
    k_dist<<<dim3(256, 2), 256>>>(w, 2048, 16, 4);
    k_up_last<<<gu, 256>>>(w, o3, o4);
}

// round 13
// speedup vs baseline: 1.5479x; 1.5479x over previous
#include <cuda_runtime.h>

#define BB 64
#define CC 32
#define KK 4096
#define NPIX (BB*CC*256)       // 524288
#define MAXTOK 16384

__device__ float g_zrest[NPIX];
__device__ float g_zflat[MAXTOK*CC];
__device__ float g_zsq[MAXTOK];
__device__ float g_wsq[KK];
__device__ float g_pd[65536];
__device__ int   g_pi[65536];
__device__ int   g_tok[MAXTOK];

typedef unsigned long long ull;

// ---------------- init: z_rest = z_enc ----------------
__global__ void k_init(const float* __restrict__ z) {
    int i = blockIdx.x * 256 + threadIdx.x;
    g_zrest[i] = z[i];
}

// ---------------- wsq[k] = sum(emb[k]^2) ----------------
__global__ void k_wsq(const float* __restrict__ w) {
    int r = blockIdx.x * 256 + threadIdx.x;
    const float* p = w + r * 32;
    float s = 0.f;
#pragma unroll
    for (int c = 0; c < 32; c++) s = __fadd_rn(s, __fmul_rn(p[c], p[c]));
    g_wsq[r] = s;
}

// ---------------- prep: area-downsample -> zflat, zsq ----------------
__global__ void k_prep(int pn) {
    int warp = threadIdx.x >> 5, lane = threadIdx.x & 31;
    int t = blockIdx.x * 8 + warp;
    int pn2 = pn * pn;
    int b = t / pn2, r = t % pn2;
    int y = r / pn, x = r % pn;
    int sub = 16 / pn;
    float inv = 1.f / (float)(sub * sub);
    const float* base = g_zrest + (((b * 32 + lane) * 16 + y * sub) * 16 + x * sub);
    float s = 0.f;
    for (int dy = 0; dy < sub; dy++)
        for (int dx = 0; dx < sub; dx++)
            s = __fadd_rn(s, base[dy * 16 + dx]);
    float zd = __fmul_rn(s, inv);
    g_zflat[t * 32 + lane] = zd;
    float q = __fmul_rn(zd, zd);
#pragma unroll
    for (int off = 16; off; off >>= 1)
        q = __fadd_rn(q, __shfl_xor_sync(0xffffffffu, q, off));
    if (lane == 0) g_zsq[t] = q;
}

// ---------------- dist+argmin via packed f32x2 FMA -------------------------
// CTA: 128 threads, tile = 64 tokens x 128 codes per iteration.
// Per thread: 8 tokens (as 4 f32x2 token-pairs) x 8 codes = 32 f32x2 accs.
// grid.x = tokens/64, grid.y = KSPLIT.
__global__ void __launch_bounds__(128) k_dist(const float* __restrict__ emb,
                                              int codesPerSplit, int iters) {
    __shared__ float zs[32][64];
    __shared__ float es[32][128];
    __shared__ float ws[128];
    int tid = threadIdx.x;
    int tx = tid & 15, ty = tid >> 4;       // tx: code group, ty: token group
    int tb = blockIdx.x * 64;

    // stage z tile (c-major): 64 tokens x 4 parts = 256 slots
    for (int s = tid; s < 256; s += 128) {
        int tok = s >> 2, part = s & 3;
        const float4* p = (const float4*)(g_zflat + (tb + tok) * 32 + part * 8);
        float4 a = p[0], b4 = p[1];
        int c0 = part * 8;
        zs[c0+0][tok]=a.x;  zs[c0+1][tok]=a.y;  zs[c0+2][tok]=a.z;  zs[c0+3][tok]=a.w;
        zs[c0+4][tok]=b4.x; zs[c0+5][tok]=b4.y; zs[c0+6][tok]=b4.z; zs[c0+7][tok]=b4.w;
    }
    float zq[8];
#pragma unroll
    for (int j = 0; j < 8; j++) zq[j] = g_zsq[tb + ty * 8 + j];

    float bd[8]; int bk[8];
#pragma unroll
    for (int j = 0; j < 8; j++) { bd[j] = __int_as_float(0x7f800000); bk[j] = 0; }

    int kbase = blockIdx.y * codesPerSplit;
    for (int it = 0; it < iters; it++) {
        int kb = kbase + it * 128;
        __syncthreads();
        // stage e tile: 128 codes x 4 parts = 512 slots
        for (int s = tid; s < 512; s += 128) {
            int code = s >> 2, part = s & 3;
            const float4* p = (const float4*)(emb + (kb + code) * 32 + part * 8);
            float4 a = p[0], b4 = p[1];
            int c0 = part * 8;
            es[c0+0][code]=a.x;  es[c0+1][code]=a.y;  es[c0+2][code]=a.z;  es[c0+3][code]=a.w;
            es[c0+4][code]=b4.x; es[c0+5][code]=b4.y; es[c0+6][code]=b4.z; es[c0+7][code]=b4.w;
        }
        ws[tid] = g_wsq[kb + tid];
        __syncthreads();

        ull acc[4][8];
#pragma unroll
        for (int p = 0; p < 4; p++)
#pragma unroll
            for (int k = 0; k < 8; k++) acc[p][k] = 0ull;

#pragma unroll 8
        for (int c = 0; c < 32; c++) {
            // 4 token-pairs, natively packed (adjacent tokens share an f32x2)
            ulonglong2 za = *(const ulonglong2*)&zs[c][ty * 8];
            ulonglong2 zb = *(const ulonglong2*)&zs[c][ty * 8 + 4];
            ull zp[4] = {za.x, za.y, zb.x, zb.y};
            // 8 codes, each duplicated into both f32x2 halves
            float4 e0 = *(const float4*)&es[c][tx * 8];
            float4 e1 = *(const float4*)&es[c][tx * 8 + 4];
            ull ed[8];
            asm("mov.b64 %0, {%1, %1};" : "=l"(ed[0]) : "f"(e0.x));
            asm("mov.b64 %0, {%1, %1};" : "=l"(ed[1]) : "f"(e0.y));
            asm("mov.b64 %0, {%1, %1};" : "=l"(ed[2]) : "f"(e0.z));
            asm("mov.b64 %0, {%1, %1};" : "=l"(ed[3]) : "f"(e0.w));
            asm("mov.b64 %0, {%1, %1};" : "=l"(ed[4]) : "f"(e1.x));
            asm("mov.b64 %0, {%1, %1};" : "=l"(ed[5]) : "f"(e1.y));
            asm("mov.b64 %0, {%1, %1};" : "=l"(ed[6]) : "f"(e1.z));
            asm("mov.b64 %0, {%1, %1};" : "=l"(ed[7]) : "f"(e1.w));
#pragma unroll
            for (int p = 0; p < 4; p++)
#pragma unroll
                for (int k = 0; k < 8; k++)
                    asm("fma.rn.f32x2 %0, %1, %2, %0;"
                        : "+l"(acc[p][k]) : "l"(zp[p]), "l"(ed[k]));
        }

        // distances + best update (codes ascending within thread -> '<' keeps first)
#pragma unroll
        for (int p = 0; p < 4; p++) {
#pragma unroll
            for (int k = 0; k < 8; k++) {
                float lo, hi;
                asm("mov.b64 {%0, %1}, %2;" : "=f"(lo), "=f"(hi) : "l"(acc[p][k]));
                int kk = kb + tx * 8 + k;
                float wv = ws[tx * 8 + k];
                float d0 = __fadd_rn(__fadd_rn(zq[2*p], wv), __fmul_rn(-2.f, lo));
                float d1 = __fadd_rn(__fadd_rn(zq[2*p+1], wv), __fmul_rn(-2.f, hi));
                if (d0 < bd[2*p])   { bd[2*p] = d0;   bk[2*p] = kk; }
                if (d1 < bd[2*p+1]) { bd[2*p+1] = d1; bk[2*p+1] = kk; }
            }
        }
    }

    // reduce across the 16 tx lanes (tie -> lowest code index)
#pragma unroll
    for (int j = 0; j < 8; j++) {
        float d = bd[j]; int k = bk[j];
#pragma unroll
        for (int off = 8; off; off >>= 1) {
            float od = __shfl_xor_sync(0xffffffffu, d, off, 16);
            int   ok = __shfl_xor_sync(0xffffffffu, k, off, 16);
            if (od < d || (od == d && ok < k)) { d = od; k = ok; }
        }
        if (tx == 0) {
            int t = tb + ty * 8 + j;
            g_pd[t * gridDim.y + blockIdx.y] = d;
            g_pi[t * gridDim.y + blockIdx.y] = k;
        }
    }
}

// ---------------- reduce over K-splits ----------------
__global__ void k_red(int N, int KS) {
    int t = blockIdx.x * 256 + threadIdx.x;
    if (t >= N) return;
    float bd = g_pd[t * KS]; int bk = g_pi[t * KS];
    for (int s = 1; s < KS; s++) {
        float d = g_pd[t * KS + s]; int k = g_pi[t * KS + s];
        if (d < bd || (d == bd && k < bk)) { bd = d; bk = k; }
    }
    g_tok[t] = bk;
}

// ---------------- cubic (jax Keys a=-0.5) weights, renormalized -------------
template<int PN>
__device__ __forceinline__ void cubw(int o, float* w) {
    if (PN == 1) { w[0] = 1.f; return; }
    float s = __fadd_rn(__fmul_rn(__fadd_rn((float)o, 0.5f), (float)PN / 16.f), -0.5f);
    float tot = 0.f;
#pragma unroll
    for (int i = 0; i < PN; i++) {
        float x = fabsf(s - (float)i);
        float v;
        if (x >= 2.f)      v = 0.f;
        else if (x >= 1.f) v = ((-0.5f * x + 2.5f) * x - 4.f) * x + 2.f;
        else               v = ((1.5f * x - 2.5f) * x) * x + 1.f;
        w[i] = v; tot += v;
    }
#pragma unroll
    for (int i = 0; i < PN; i++) w[i] = w[i] / tot;
}

// ---------------- gather + bicubic up + residual update (levels 0..3) -------
template<int PN>
__global__ void __launch_bounds__(256) k_up(const float* __restrict__ emb,
                                            const float* __restrict__ outPrev,
                                            float* __restrict__ outCur,
                                            int isFirst) {
    __shared__ float ew[PN * PN][32];
    int b = blockIdx.x;
    int tid = threadIdx.x;
    for (int idx = tid; idx < PN * PN * 8; idx += 256) {
        int token = idx >> 3, seg = idx & 7;
        int code = g_tok[b * PN * PN + token];
        float4 v = *(const float4*)(emb + code * 32 + seg * 4);
        *(float4*)&ew[token][seg * 4] = v;
    }
    __syncthreads();
    int y = tid >> 4, x = tid & 15;
    float wy[PN], wx[PN];
    cubw<PN>(y, wy);
    cubw<PN>(x, wx);
#pragma unroll
    for (int c = 0; c < 32; c++) {
        float acc = 0.f;
#pragma unroll
        for (int j = 0; j < PN; j++) {
            float tmp = 0.f;
#pragma unroll
            for (int i = 0; i < PN; i++) tmp += wx[i] * ew[j * PN + i][c];
            acc += wy[j] * tmp;
        }
        int idx = (b * 32 + c) * 256 + y * 16 + x;
        float prev = isFirst ? 0.f : outPrev[idx];
        outCur[idx] = prev + acc;
        g_zrest[idx] = g_zrest[idx] - acc;
    }
}

// ---------------- last level: plain gather + accumulate ----------------
__global__ void k_up_last(const float* __restrict__ emb,
                          const float* __restrict__ outPrev,
                          float* __restrict__ outCur) {
    int b = blockIdx.x, tid = threadIdx.x;
    int tok = g_tok[b * 256 + tid];
    const float* e = emb + tok * 32;
#pragma unroll
    for (int c = 0; c < 32; c++) {
        int idx = (b * 32 + c) * 256 + tid;
        outCur[idx] = outPrev[idx] + e[c];
    }
}

extern "C" void kernel_launch(void* const* d_in, const int* in_sizes, int n_in,
                              void* d_out, int out_size) {
    const float* z = (const float*)d_in[0];     // z_enc [64,32,16,16]
    const float* w = (const float*)d_in[1];     // emb_weight [4096,32]
    float* out = (float*)d_out;                 // [5,64,32,16,16]

    k_init<<<NPIX / 256, 256>>>(z);
    k_wsq<<<KK / 256, 256>>>(w);

    const int pns[5]     = {1, 2, 4, 8, 16};
    const int ksplits[5] = {32, 32, 16, 8, 4};   // was {32,16,8,4,2}: 2x warps/SMSP on L3/L4

    for (int l = 0; l < 5; l++) {
        int pn = pns[l];
        int N = 64 * pn * pn;
        k_prep<<<N / 8, 256>>>(pn);

        int KS = ksplits[l];
        int codesPerSplit = KK / KS;
        int iters = codesPerSplit / 128;
        dim3 g(N / 64, KS);
        k_dist<<<g, 128>>>(w, codesPerSplit, iters);
        k_red<<<(N + 255) / 256, 256>>>(N, KS);

        float* cur = out + (size_t)l * NPIX;
        const float* prev = (l == 0) ? out : out + (size_t)(l - 1) * NPIX;
        if      (l == 0) k_up<1><<<64, 256>>>(w, prev, cur, 1);
        else if (l == 1) k_up<2><<<64, 256>>>(w, prev, cur, 0);
        else if (l == 2) k_up<4><<<64, 256>>>(w, prev, cur, 0);
        else if (l == 3) k_up<8><<<64, 256>>>(w, prev, cur, 0);
        else             k_up_last<<<64, 256>>>(w, prev, cur);
    }
}

// round 14
// speedup vs baseline: 1.7028x; 1.1001x over previous
#include <cuda_runtime.h>

#define BB 64
#define CC 32
#define KK 4096
#define NPIX (BB*CC*256)
#define MAXTOK 16384
#define POSINF __int_as_float(0x7f800000)

__device__ float g_zrest[NPIX];
__device__ float g_zflat[MAXTOK*CC];
__device__ float g_zsq[MAXTOK];
__device__ float g_wsq[KK];
__device__ float g_pd[65536];
__device__ int   g_pi[65536];

typedef unsigned long long ull;

// ---------- fused init: zrest copy + wsq + level-0 prep ----------
__global__ void k_init(const float* __restrict__ z, const float* __restrict__ w) {
    int bid = blockIdx.x, tid = threadIdx.x;
    if (bid < 2048) {
        int i = bid * 256 + tid;
        g_zrest[i] = z[i];
    } else if (bid < 2064) {
        int r = (bid - 2048) * 256 + tid;
        const float* p = w + r * 32;
        float s = 0.f;
#pragma unroll
        for (int c = 0; c < 32; c++) s = __fadd_rn(s, __fmul_rn(p[c], p[c]));
        g_wsq[r] = s;
    } else {
        int warp = tid >> 5, lane = tid & 31;
        int t = (bid - 2064) * 8 + warp;          // 0..63
        const float* base = z + (t * 32 + lane) * 256;
        float s = 0.f;
        for (int dy = 0; dy < 16; dy++)
            for (int dx = 0; dx < 16; dx++)
                s = __fadd_rn(s, base[dy * 16 + dx]);
        float zd = __fmul_rn(s, 1.f / 256.f);
        g_zflat[t * 32 + lane] = zd;
        float q = __fmul_rn(zd, zd);
#pragma unroll
        for (int off = 16; off; off >>= 1)
            q = __fadd_rn(q, __shfl_xor_sync(0xffffffffu, q, off));
        if (lane == 0) g_zsq[t] = q;
    }
}

// ---------- dist+argmin (R13 engine, unchanged): 64 tok x 128 codes ----------
__global__ void __launch_bounds__(128) k_dist(const float* __restrict__ emb,
                                              int codesPerSplit, int iters) {
    __shared__ float zs[32][64];
    __shared__ float es[32][128];
    __shared__ float ws[128];
    int tid = threadIdx.x;
    int tx = tid & 15, ty = tid >> 4;
    int tb = blockIdx.x * 64;

    for (int s = tid; s < 256; s += 128) {
        int tok = s >> 2, part = s & 3;
        const float4* p = (const float4*)(g_zflat + (tb + tok) * 32 + part * 8);
        float4 a = p[0], b4 = p[1];
        int c0 = part * 8;
        zs[c0+0][tok]=a.x;  zs[c0+1][tok]=a.y;  zs[c0+2][tok]=a.z;  zs[c0+3][tok]=a.w;
        zs[c0+4][tok]=b4.x; zs[c0+5][tok]=b4.y; zs[c0+6][tok]=b4.z; zs[c0+7][tok]=b4.w;
    }
    float zq[8];
#pragma unroll
    for (int j = 0; j < 8; j++) zq[j] = g_zsq[tb + ty * 8 + j];

    float bd[8]; int bk[8];
#pragma unroll
    for (int j = 0; j < 8; j++) { bd[j] = POSINF; bk[j] = 0; }

    int kbase = blockIdx.y * codesPerSplit;
    for (int it = 0; it < iters; it++) {
        int kb = kbase + it * 128;
        __syncthreads();
        for (int s = tid; s < 512; s += 128) {
            int code = s >> 2, part = s & 3;
            const float4* p = (const float4*)(emb + (kb + code) * 32 + part * 8);
            float4 a = p[0], b4 = p[1];
            int c0 = part * 8;
            es[c0+0][code]=a.x;  es[c0+1][code]=a.y;  es[c0+2][code]=a.z;  es[c0+3][code]=a.w;
            es[c0+4][code]=b4.x; es[c0+5][code]=b4.y; es[c0+6][code]=b4.z; es[c0+7][code]=b4.w;
        }
        ws[tid] = g_wsq[kb + tid];
        __syncthreads();

        ull acc[4][8];
#pragma unroll
        for (int p = 0; p < 4; p++)
#pragma unroll
            for (int k = 0; k < 8; k++) acc[p][k] = 0ull;

#pragma unroll 8
        for (int c = 0; c < 32; c++) {
            ulonglong2 za = *(const ulonglong2*)&zs[c][ty * 8];
            ulonglong2 zb = *(const ulonglong2*)&zs[c][ty * 8 + 4];
            ull zp[4] = {za.x, za.y, zb.x, zb.y};
            float4 e0 = *(const float4*)&es[c][tx * 8];
            float4 e1 = *(const float4*)&es[c][tx * 8 + 4];
            ull ed[8];
            asm("mov.b64 %0, {%1, %1};" : "=l"(ed[0]) : "f"(e0.x));
            asm("mov.b64 %0, {%1, %1};" : "=l"(ed[1]) : "f"(e0.y));
            asm("mov.b64 %0, {%1, %1};" : "=l"(ed[2]) : "f"(e0.z));
            asm("mov.b64 %0, {%1, %1};" : "=l"(ed[3]) : "f"(e0.w));
            asm("mov.b64 %0, {%1, %1};" : "=l"(ed[4]) : "f"(e1.x));
            asm("mov.b64 %0, {%1, %1};" : "=l"(ed[5]) : "f"(e1.y));
            asm("mov.b64 %0, {%1, %1};" : "=l"(ed[6]) : "f"(e1.z));
            asm("mov.b64 %0, {%1, %1};" : "=l"(ed[7]) : "f"(e1.w));
#pragma unroll
            for (int p = 0; p < 4; p++)
#pragma unroll
                for (int k = 0; k < 8; k++)
                    asm("fma.rn.f32x2 %0, %1, %2, %0;"
                        : "+l"(acc[p][k]) : "l"(zp[p]), "l"(ed[k]));
        }

#pragma unroll
        for (int p = 0; p < 4; p++) {
#pragma unroll
            for (int k = 0; k < 8; k++) {
                float lo, hi;
                asm("mov.b64 {%0, %1}, %2;" : "=f"(lo), "=f"(hi) : "l"(acc[p][k]));
                int kk = kb + tx * 8 + k;
                float wv = ws[tx * 8 + k];
                float d0 = __fadd_rn(__fadd_rn(zq[2*p],   wv), __fmul_rn(-2.f, lo));
                float d1 = __fadd_rn(__fadd_rn(zq[2*p+1], wv), __fmul_rn(-2.f, hi));
                if (d0 < bd[2*p])   { bd[2*p]   = d0; bk[2*p]   = kk; }
                if (d1 < bd[2*p+1]) { bd[2*p+1] = d1; bk[2*p+1] = kk; }
            }
        }
    }

#pragma unroll
    for (int j = 0; j < 8; j++) {
        float d = bd[j]; int k = bk[j];
#pragma unroll
        for (int off = 8; off; off >>= 1) {
            float od = __shfl_xor_sync(0xffffffffu, d, off, 16);
            int   ok = __shfl_xor_sync(0xffffffffu, k, off, 16);
            if (od < d || (od == d && ok < k)) { d = od; k = ok; }
        }
        if (tx == 0) {
            int t = tb + ty * 8 + j;
            g_pd[t * gridDim.y + blockIdx.y] = d;
            g_pi[t * gridDim.y + blockIdx.y] = k;
        }
    }
}

// ---------- cubic (jax Keys a=-0.5) weights, renormalized ----------
template<int PN>
__device__ __forceinline__ void cubw(int o, float* w) {
    if (PN == 1) { w[0] = 1.f; return; }
    float s = __fadd_rn(__fmul_rn(__fadd_rn((float)o, 0.5f), (float)PN / 16.f), -0.5f);
    float tot = 0.f;
#pragma unroll
    for (int i = 0; i < PN; i++) {
        float x = fabsf(s - (float)i);
        float v;
        if (x >= 2.f)      v = 0.f;
        else if (x >= 1.f) v = ((-0.5f * x + 2.5f) * x - 4.f) * x + 2.f;
        else               v = ((1.5f * x - 2.5f) * x) * x + 1.f;
        w[i] = v; tot += v;
    }
#pragma unroll
    for (int i = 0; i < PN; i++) w[i] = w[i] / tot;
}

// ---------- fused: ksplit-reduce + gather + bicubic + zrest + next prep -----
template<int PN, int PNN>
__global__ void __launch_bounds__(256) k_up(const float* __restrict__ emb,
                                            const float* __restrict__ outPrev,
                                            float* __restrict__ outCur,
                                            int isFirst, int KS) {
    constexpr int NT = PN * PN;
    constexpr int SUB = 16 / PNN;
    __shared__ float pdp[512];
    __shared__ int   pip[512];
    __shared__ int   tok_s[NT];
    __shared__ float ew[NT][33];
    __shared__ float zt[32][256];
    int b = blockIdx.x;
    int tid = threadIdx.x;

    int tot = NT * KS;
    for (int i = tid; i < tot; i += 256) {
        pdp[i] = g_pd[b * tot + i];
        pip[i] = g_pi[b * tot + i];
    }
    __syncthreads();
    if (tid < NT) {
        float bdv = pdp[tid * KS]; int bkv = pip[tid * KS];
        for (int s = 1; s < KS; s++) {
            float d = pdp[tid * KS + s]; int k = pip[tid * KS + s];
            if (d < bdv || (d == bdv && k < bkv)) { bdv = d; bkv = k; }
        }
        tok_s[tid] = bkv;
    }
    __syncthreads();

    for (int idx = tid; idx < NT * 8; idx += 256) {
        int token = idx >> 3, seg = idx & 7;
        float4 v = *(const float4*)(emb + tok_s[token] * 32 + seg * 4);
        ew[token][seg*4+0] = v.x; ew[token][seg*4+1] = v.y;
        ew[token][seg*4+2] = v.z; ew[token][seg*4+3] = v.w;
    }
    __syncthreads();

    int y = tid >> 4, x = tid & 15;
    float wy[PN], wx[PN];
    cubw<PN>(y, wy);
    cubw<PN>(x, wx);
#pragma unroll
    for (int c = 0; c < 32; c++) {
        float acc = 0.f;
#pragma unroll
        for (int j = 0; j < PN; j++) {
            float tmp = 0.f;
#pragma unroll
            for (int i = 0; i < PN; i++) tmp += wx[i] * ew[j * PN + i][c];
            acc += wy[j] * tmp;
        }
        int idx = (b * 32 + c) * 256 + y * 16 + x;
        float prev = isFirst ? 0.f : outPrev[idx];
        outCur[idx] = prev + acc;
        float nz = g_zrest[idx] - acc;
        g_zrest[idx] = nz;
        zt[c][tid] = nz;
    }
    __syncthreads();

    if (tid < PNN * PNN) {
        int ty2 = tid / PNN, tx2 = tid % PNN;
        float buf[32];
        float zqacc = 0.f;
#pragma unroll
        for (int c = 0; c < 32; c++) {
            float s = 0.f;
            for (int dy = 0; dy < SUB; dy++)
                for (int dx = 0; dx < SUB; dx++)
                    s = __fadd_rn(s, zt[c][(ty2 * SUB + dy) * 16 + tx2 * SUB + dx]);
            float zd = __fmul_rn(s, 1.f / (float)(SUB * SUB));
            buf[c] = zd;
            zqacc = __fadd_rn(zqacc, __fmul_rn(zd, zd));
        }
        int row = b * PNN * PNN + tid;
        float* dst = g_zflat + (size_t)row * 32;
#pragma unroll
        for (int s8 = 0; s8 < 8; s8++)
            *(float4*)(dst + s8 * 4) = make_float4(buf[s8*4], buf[s8*4+1],
                                                   buf[s8*4+2], buf[s8*4+3]);
        g_zsq[row] = zqacc;
    }
}

// ---------- last level: fused reduce + gather + accumulate ----------
__global__ void __launch_bounds__(256) k_up_last(const float* __restrict__ emb,
                                                 const float* __restrict__ outPrev,
                                                 float* __restrict__ outCur, int KS) {
    __shared__ float pdp[1024];
    __shared__ int   pip[1024];
    __shared__ int   tok_s[256];
    int b = blockIdx.x, tid = threadIdx.x;
    int tot = 256 * KS;
    for (int i = tid; i < tot; i += 256) {
        pdp[i] = g_pd[b * tot + i];
        pip[i] = g_pi[b * tot + i];
    }
    __syncthreads();
    {
        float bdv = pdp[tid * KS]; int bkv = pip[tid * KS];
        for (int s = 1; s < KS; s++) {
            float d = pdp[tid * KS + s]; int k = pip[tid * KS + s];
            if (d < bdv || (d == bdv && k < bkv)) { bdv = d; bkv = k; }
        }
        tok_s[tid] = bkv;
    }
    __syncthreads();
    const float* e = emb + tok_s[tid] * 32;
#pragma unroll
    for (int c = 0; c < 32; c++) {
        int idx = (b * 32 + c) * 256 + tid;
        outCur[idx] = outPrev[idx] + e[c];
    }
}

extern "C" void kernel_launch(void* const* d_in, const int* in_sizes, int n_in,
                              void* d_out, int out_size) {
    const float* z = (const float*)d_in[0];
    const float* w = (const float*)d_in[1];
    float* out = (float*)d_out;

    k_init<<<2072, 256>>>(z, w);

    const int ntok[5] = {64, 256, 1024, 4096, 16384};
    const int KSs[5]  = {32, 32, 16, 8, 4};

    for (int l = 0; l < 5; l++) {
        int KS = KSs[l];
        int cps = KK / KS;
        int iters = cps / 128;
        dim3 g(ntok[l] / 64, KS);
        k_dist<<<g, 128>>>(w, cps, iters);

        float* cur = out + (size_t)l * NPIX;
        const float* prev = (l == 0) ? out : out + (size_t)(l - 1) * NPIX;
        if      (l == 0) k_up<1, 2 ><<<64, 256>>>(w, prev, cur, 1, KS);
        else if (l == 1) k_up<2, 4 ><<<64, 256>>>(w, prev, cur, 0, KS);
        else if (l == 2) k_up<4, 8 ><<<64, 256>>>(w, prev, cur, 0, KS);
        else if (l == 3) k_up<8, 16><<<64, 256>>>(w, prev, cur, 0, KS);
        else             k_up_last<<<64, 256>>>(w, prev, cur, KS);
    }
}

// round 15
// speedup vs baseline: 1.7403x; 1.0220x over previous
#include <cuda_runtime.h>

#define KK 4096
#define NPIX (64*32*256)
#define POSINF __int_as_float(0x7f800000)
#define OFF1 64
#define OFF2 320
#define OFF3 1344
#define OFF4 5440

__device__ float g_zrest[NPIX];
__device__ float g_zflat[22016*32];
__device__ float g_zsq[22016];
__device__ float g_wsq[KK];
__device__ float g_pd[65536];
__device__ int   g_pi[65536];

typedef unsigned long long ull;

// ---------- cubic (jax Keys a=-0.5) weights, renormalized ----------
template<int PN>
__device__ __forceinline__ void cubw(int o, float* w) {
    if (PN == 1) { w[0] = 1.f; return; }
    float s = __fadd_rn(__fmul_rn(__fadd_rn((float)o, 0.5f), (float)PN / 16.f), -0.5f);
    float tot = 0.f;
#pragma unroll
    for (int i = 0; i < PN; i++) {
        float x = fabsf(s - (float)i);
        float v;
        if (x >= 2.f)      v = 0.f;
        else if (x >= 1.f) v = ((-0.5f * x + 2.5f) * x - 4.f) * x + 2.f;
        else               v = ((1.5f * x - 2.5f) * x) * x + 1.f;
        w[i] = v; tot += v;
    }
#pragma unroll
    for (int i = 0; i < PN; i++) w[i] = w[i] / tot;
}

// ---------- shared up-phase: gather + bicubic + zrest + next-level prep -----
template<int PN, int PNN>
__device__ void up_phase(int b, const int* tok_s, const float* __restrict__ emb,
                         const float* __restrict__ outPrev, float* __restrict__ outCur,
                         int isFirst, int wOff, const float* __restrict__ zrestSrc) {
    constexpr int NT = PN * PN;
    constexpr int SUB = 16 / PNN;
    __shared__ float ew[NT][33];
    __shared__ float zt[32][256];
    int tid = threadIdx.x;

    for (int idx = tid; idx < NT * 8; idx += 256) {
        int token = idx >> 3, seg = idx & 7;
        float4 v = *(const float4*)(emb + tok_s[token] * 32 + seg * 4);
        ew[token][seg*4+0] = v.x; ew[token][seg*4+1] = v.y;
        ew[token][seg*4+2] = v.z; ew[token][seg*4+3] = v.w;
    }
    __syncthreads();

    int y = tid >> 4, x = tid & 15;
    float wy[PN], wx[PN];
    cubw<PN>(y, wy);
    cubw<PN>(x, wx);
#pragma unroll
    for (int c = 0; c < 32; c++) {
        float acc = 0.f;
#pragma unroll
        for (int j = 0; j < PN; j++) {
            float tmp = 0.f;
#pragma unroll
            for (int i = 0; i < PN; i++) tmp += wx[i] * ew[j * PN + i][c];
            acc += wy[j] * tmp;
        }
        int idx = (b * 32 + c) * 256 + y * 16 + x;
        float prev = isFirst ? 0.f : outPrev[idx];
        outCur[idx] = prev + acc;
        float nz = zrestSrc[idx] - acc;
        g_zrest[idx] = nz;
        zt[c][tid] = nz;
    }
    __syncthreads();

    if (tid < PNN * PNN) {
        int ty2 = tid / PNN, tx2 = tid % PNN;
        float buf[32];
        float zqacc = 0.f;
#pragma unroll
        for (int c = 0; c < 32; c++) {
            float s = 0.f;
            for (int dy = 0; dy < SUB; dy++)
                for (int dx = 0; dx < SUB; dx++)
                    s = __fadd_rn(s, zt[c][(ty2 * SUB + dy) * 16 + tx2 * SUB + dx]);
            float zd = __fmul_rn(s, 1.f / (float)(SUB * SUB));
            buf[c] = zd;
            zqacc = __fadd_rn(zqacc, __fmul_rn(zd, zd));
        }
        int row = wOff + b * PNN * PNN + tid;
        float* dst = g_zflat + (size_t)row * 32;
#pragma unroll
        for (int s8 = 0; s8 < 8; s8++)
            *(float4*)(dst + s8 * 4) = make_float4(buf[s8*4], buf[s8*4+1],
                                                   buf[s8*4+2], buf[s8*4+3]);
        g_zsq[row] = zqacc;
    }
}

// ---------- level 0: downsample + wsq + dist + up + L1 prep (one kernel) ----
__global__ void __launch_bounds__(256) k_lvl0(const float* __restrict__ z,
                                              const float* __restrict__ emb,
                                              float* __restrict__ out0) {
    __shared__ float zds[32];
    __shared__ float zqs;
    __shared__ float pdw[8];
    __shared__ int   piw[8];
    __shared__ int   tok_s[1];
    int b = blockIdx.x, tid = threadIdx.x;
    int wid = tid >> 5, lane = tid & 31;

    if (tid < 32) {
        const float* base = z + (b * 32 + tid) * 256;
        float s = 0.f;
        for (int i = 0; i < 256; i++) s = __fadd_rn(s, base[i]);
        float zd = __fmul_rn(s, 1.f / 256.f);
        zds[tid] = zd;
        float q = __fmul_rn(zd, zd);
#pragma unroll
        for (int off = 16; off; off >>= 1)
            q = __fadd_rn(q, __shfl_xor_sync(0xffffffffu, q, off));
        if (tid == 0) zqs = q;
    }
    __syncthreads();

    float zr[32];
#pragma unroll
    for (int c = 0; c < 32; c++) zr[c] = zds[c];
    float zq = zqs;

    float bd = POSINF; int bk = 0;
    for (int kk = 0; kk < 16; kk++) {
        int k = tid * 16 + kk;
        const float4* e4 = (const float4*)(emb + k * 32);
        float ws = 0.f, dot = 0.f;
#pragma unroll
        for (int s8 = 0; s8 < 8; s8++) {
            float4 w4 = e4[s8];
            ws = __fadd_rn(ws, __fmul_rn(w4.x, w4.x)); dot = __fmaf_rn(zr[s8*4+0], w4.x, dot);
            ws = __fadd_rn(ws, __fmul_rn(w4.y, w4.y)); dot = __fmaf_rn(zr[s8*4+1], w4.y, dot);
            ws = __fadd_rn(ws, __fmul_rn(w4.z, w4.z)); dot = __fmaf_rn(zr[s8*4+2], w4.z, dot);
            ws = __fadd_rn(ws, __fmul_rn(w4.w, w4.w)); dot = __fmaf_rn(zr[s8*4+3], w4.w, dot);
        }
        if (b == 0) g_wsq[k] = ws;
        float d = __fadd_rn(__fadd_rn(zq, ws), __fmul_rn(-2.f, dot));
        if (d < bd) { bd = d; bk = k; }
    }
#pragma unroll
    for (int off = 16; off; off >>= 1) {
        float od = __shfl_xor_sync(0xffffffffu, bd, off);
        int   ok = __shfl_xor_sync(0xffffffffu, bk, off);
        if (od < bd || (od == bd && ok < bk)) { bd = od; bk = ok; }
    }
    if (lane == 0) { pdw[wid] = bd; piw[wid] = bk; }
    __syncthreads();
    if (tid == 0) {
        float bdv = pdw[0]; int bkv = piw[0];
        for (int wd = 1; wd < 8; wd++)
            if (pdw[wd] < bdv || (pdw[wd] == bdv && piw[wd] < bkv)) { bdv = pdw[wd]; bkv = piw[wd]; }
        tok_s[0] = bkv;
    }
    __syncthreads();

    up_phase<1, 2>(b, tok_s, emb, out0, out0, 1, OFF1, z);
}

// ---------- level 1: dist (4 tokens) + up + L2 prep (one kernel) ----------
__global__ void __launch_bounds__(256) k_lvl1(const float* __restrict__ emb,
                                              const float* __restrict__ out0,
                                              float* __restrict__ out1) {
    __shared__ float zsm[4][32];
    __shared__ float zqsm[4];
    __shared__ float pdw[8][4];
    __shared__ int   piw[8][4];
    __shared__ int   tok_s[4];
    int b = blockIdx.x, tid = threadIdx.x;
    int wid = tid >> 5, lane = tid & 31;

    if (tid < 128)
        zsm[tid >> 5][tid & 31] = g_zflat[(size_t)(OFF1 + b * 4 + (tid >> 5)) * 32 + (tid & 31)];
    if (tid < 4) zqsm[tid] = g_zsq[OFF1 + b * 4 + tid];
    __syncthreads();

    int t = tid & 3, g = tid >> 2;     // 64 code groups x 4 tokens
    float zr[32];
#pragma unroll
    for (int c = 0; c < 32; c++) zr[c] = zsm[t][c];
    float zq = zqsm[t];

    float bd = POSINF; int bk = 0;
    for (int kk = 0; kk < 64; kk++) {
        int k = g * 64 + kk;
        const float4* e4 = (const float4*)(emb + k * 32);
        float dot = 0.f;
#pragma unroll
        for (int s8 = 0; s8 < 8; s8++) {
            float4 w4 = e4[s8];
            dot = __fmaf_rn(zr[s8*4+0], w4.x, dot);
            dot = __fmaf_rn(zr[s8*4+1], w4.y, dot);
            dot = __fmaf_rn(zr[s8*4+2], w4.z, dot);
            dot = __fmaf_rn(zr[s8*4+3], w4.w, dot);
        }
        float d = __fadd_rn(__fadd_rn(zq, g_wsq[k]), __fmul_rn(-2.f, dot));
        if (d < bd) { bd = d; bk = k; }
    }
#pragma unroll
    for (int off = 4; off <= 16; off <<= 1) {
        float od = __shfl_xor_sync(0xffffffffu, bd, off);
        int   ok = __shfl_xor_sync(0xffffffffu, bk, off);
        if (od < bd || (od == bd && ok < bk)) { bd = od; bk = ok; }
    }
    if (lane < 4) { pdw[wid][lane] = bd; piw[wid][lane] = bk; }
    __syncthreads();
    if (tid < 4) {
        float bdv = pdw[0][tid]; int bkv = piw[0][tid];
        for (int wd = 1; wd < 8; wd++)
            if (pdw[wd][tid] < bdv || (pdw[wd][tid] == bdv && piw[wd][tid] < bkv))
                { bdv = pdw[wd][tid]; bkv = piw[wd][tid]; }
        tok_s[tid] = bkv;
    }
    __syncthreads();

    up_phase<2, 4>(b, tok_s, emb, out0, out1, 0, OFF2, g_zrest);
}

// ---------- dist+argmin (R13/R14 engine + rowOff): 64 tok x 128 codes -------
__global__ void __launch_bounds__(128) k_dist(const float* __restrict__ emb,
                                              int codesPerSplit, int iters, int rowOff) {
    __shared__ float zs[32][64];
    __shared__ float es[32][128];
    __shared__ float ws[128];
    int tid = threadIdx.x;
    int tx = tid & 15, ty = tid >> 4;
    int tb = blockIdx.x * 64;

    for (int s = tid; s < 256; s += 128) {
        int tok = s >> 2, part = s & 3;
        const float4* p = (const float4*)(g_zflat + (size_t)(rowOff + tb + tok) * 32 + part * 8);
        float4 a = p[0], b4 = p[1];
        int c0 = part * 8;
        zs[c0+0][tok]=a.x;  zs[c0+1][tok]=a.y;  zs[c0+2][tok]=a.z;  zs[c0+3][tok]=a.w;
        zs[c0+4][tok]=b4.x; zs[c0+5][tok]=b4.y; zs[c0+6][tok]=b4.z; zs[c0+7][tok]=b4.w;
    }
    float zq[8];
#pragma unroll
    for (int j = 0; j < 8; j++) zq[j] = g_zsq[rowOff + tb + ty * 8 + j];

    float bd[8]; int bk[8];
#pragma unroll
    for (int j = 0; j < 8; j++) { bd[j] = POSINF; bk[j] = 0; }

    int kbase = blockIdx.y * codesPerSplit;
    for (int it = 0; it < iters; it++) {
        int kb = kbase + it * 128;
        __syncthreads();
        for (int s = tid; s < 512; s += 128) {
            int code = s >> 2, part = s & 3;
            const float4* p = (const float4*)(emb + (kb + code) * 32 + part * 8);
            float4 a = p[0], b4 = p[1];
            int c0 = part * 8;
            es[c0+0][code]=a.x;  es[c0+1][code]=a.y;  es[c0+2][code]=a.z;  es[c0+3][code]=a.w;
            es[c0+4][code]=b4.x; es[c0+5][code]=b4.y; es[c0+6][code]=b4.z; es[c0+7][code]=b4.w;
        }
        ws[tid] = g_wsq[kb + tid];
        __syncthreads();

        ull acc[4][8];
#pragma unroll
        for (int p = 0; p < 4; p++)
#pragma unroll
            for (int k = 0; k < 8; k++) acc[p][k] = 0ull;

#pragma unroll 8
        for (int c = 0; c < 32; c++) {
            ulonglong2 za = *(const ulonglong2*)&zs[c][ty * 8];
            ulonglong2 zb = *(const ulonglong2*)&zs[c][ty * 8 + 4];
            ull zp[4] = {za.x, za.y, zb.x, zb.y};
            float4 e0 = *(const float4*)&es[c][tx * 8];
            float4 e1 = *(const float4*)&es[c][tx * 8 + 4];
            ull ed[8];
            asm("mov.b64 %0, {%1, %1};" : "=l"(ed[0]) : "f"(e0.x));
            asm("mov.b64 %0, {%1, %1};" : "=l"(ed[1]) : "f"(e0.y));
            asm("mov.b64 %0, {%1, %1};" : "=l"(ed[2]) : "f"(e0.z));
            asm("mov.b64 %0, {%1, %1};" : "=l"(ed[3]) : "f"(e0.w));
            asm("mov.b64 %0, {%1, %1};" : "=l"(ed[4]) : "f"(e1.x));
            asm("mov.b64 %0, {%1, %1};" : "=l"(ed[5]) : "f"(e1.y));
            asm("mov.b64 %0, {%1, %1};" : "=l"(ed[6]) : "f"(e1.z));
            asm("mov.b64 %0, {%1, %1};" : "=l"(ed[7]) : "f"(e1.w));
#pragma unroll
            for (int p = 0; p < 4; p++)
#pragma unroll
                for (int k = 0; k < 8; k++)
                    asm("fma.rn.f32x2 %0, %1, %2, %0;"
                        : "+l"(acc[p][k]) : "l"(zp[p]), "l"(ed[k]));
        }

#pragma unroll
        for (int p = 0; p < 4; p++) {
#pragma unroll
            for (int k = 0; k < 8; k++) {
                float lo, hi;
                asm("mov.b64 {%0, %1}, %2;" : "=f"(lo), "=f"(hi) : "l"(acc[p][k]));
                int kk = kb + tx * 8 + k;
                float wv = ws[tx * 8 + k];
                float d0 = __fadd_rn(__fadd_rn(zq[2*p],   wv), __fmul_rn(-2.f, lo));
                float d1 = __fadd_rn(__fadd_rn(zq[2*p+1], wv), __fmul_rn(-2.f, hi));
                if (d0 < bd[2*p])   { bd[2*p]   = d0; bk[2*p]   = kk; }
                if (d1 < bd[2*p+1]) { bd[2*p+1] = d1; bk[2*p+1] = kk; }
            }
        }
    }

#pragma unroll
    for (int j = 0; j < 8; j++) {
        float d = bd[j]; int k = bk[j];
#pragma unroll
        for (int off = 8; off; off >>= 1) {
            float od = __shfl_xor_sync(0xffffffffu, d, off, 16);
            int   ok = __shfl_xor_sync(0xffffffffu, k, off, 16);
            if (od < d || (od == d && ok < k)) { d = od; k = ok; }
        }
        if (tx == 0) {
            int t = tb + ty * 8 + j;
            g_pd[t * gridDim.y + blockIdx.y] = d;
            g_pi[t * gridDim.y + blockIdx.y] = k;
        }
    }
}

// ---------- k_up: ksplit-reduce + up_phase (levels 2,3) ----------
template<int PN, int PNN>
__global__ void __launch_bounds__(256) k_up(const float* __restrict__ emb,
                                            const float* __restrict__ outPrev,
                                            float* __restrict__ outCur,
                                            int KS, int wOff) {
    constexpr int NT = PN * PN;
    __shared__ float pdp[512];
    __shared__ int   pip[512];
    __shared__ int   tok_s[NT];
    int b = blockIdx.x, tid = threadIdx.x;

    int tot = NT * KS;
    for (int i = tid; i < tot; i += 256) {
        pdp[i] = g_pd[b * tot + i];
        pip[i] = g_pi[b * tot + i];
    }
    __syncthreads();
    if (tid < NT) {
        float bdv = pdp[tid * KS]; int bkv = pip[tid * KS];
        for (int s = 1; s < KS; s++) {
            float d = pdp[tid * KS + s]; int k = pip[tid * KS + s];
            if (d < bdv || (d == bdv && k < bkv)) { bdv = d; bkv = k; }
        }
        tok_s[tid] = bkv;
    }
    __syncthreads();

    up_phase<PN, PNN>(b, tok_s, emb, outPrev, outCur, 0, wOff, g_zrest);
}

// ---------- last level: reduce + gather + accumulate ----------
__global__ void __launch_bounds__(256) k_up_last(const float* __restrict__ emb,
                                                 const float* __restrict__ outPrev,
                                                 float* __restrict__ outCur, int KS) {
    __shared__ float pdp[1024];
    __shared__ int   pip[1024];
    __shared__ int   tok_s[256];
    int b = blockIdx.x, tid = threadIdx.x;
    int tot = 256 * KS;
    for (int i = tid; i < tot; i += 256) {
        pdp[i] = g_pd[b * tot + i];
        pip[i] = g_pi[b * tot + i];
    }
    __syncthreads();
    {
        float bdv = pdp[tid * KS]; int bkv = pip[tid * KS];
        for (int s = 1; s < KS; s++) {
            float d = pdp[tid * KS + s]; int k = pip[tid * KS + s];
            if (d < bdv || (d == bdv && k < bkv)) { bdv = d; bkv = k; }
        }
        tok_s[tid] = bkv;
    }
    __syncthreads();
    const float* e = emb + tok_s[tid] * 32;
#pragma unroll
    for (int c = 0; c < 32; c++) {
        int idx = (b * 32 + c) * 256 + tid;
        outCur[idx] = outPrev[idx] + e[c];
    }
}

extern "C" void kernel_launch(void* const* d_in, const int* in_sizes, int n_in,
                              void* d_out, int out_size) {
    const float* z = (const float*)d_in[0];
    const float* w = (const float*)d_in[1];
    float* out = (float*)d_out;
    float* o0 = out;
    float* o1 = out + (size_t)NPIX;
    float* o2 = out + 2 * (size_t)NPIX;
    float* o3 = out + 3 * (size_t)NPIX;
    float* o4 = out + 4 * (size_t)NPIX;

    // L0 + L1: fully fused (downsample + wsq + dist + up + next-level prep)
    k_lvl0<<<64, 256>>>(z, w, o0);
    k_lvl1<<<64, 256>>>(w, o0, o1);

    // L2: 1024 tokens, KS=16
    k_dist<<<dim3(16, 16), 128>>>(w, 256, 2, OFF2);
    k_up<4, 8><<<64, 256>>>(w, o1, o2, 16, OFF3);

    // L3: 4096 tokens, KS=8
    k_dist<<<dim3(64, 8), 128>>>(w, 512, 4, OFF3);
    k_up<8, 16><<<64, 256>>>(w, o2, o3, 8, OFF4);

    // L4: 16384 tokens, KS=4
    k_dist<<<dim3(256, 4), 128>>>(w, 1024, 8, OFF4);
    k_up_last<<<64, 256>>>(w, o3, o4, 4);
}

// round 16
// speedup vs baseline: 1.8546x; 1.0657x over previous
#include <cuda_runtime.h>

#define KK 4096
#define NPIX (64*32*256)
#define POSINF __int_as_float(0x7f800000)
#define OFF1 64
#define OFF2 320
#define OFF3 1344
#define OFF4 5440

__device__ float g_zrest[NPIX];
__device__ float g_zflat[22016*32];
__device__ float g_zsq[22016];
__device__ float g_wsq[KK];
__device__ float g_pd[65536];
__device__ int   g_pi[65536];

typedef unsigned long long ull;

// ---------- cubic (jax Keys a=-0.5) weights, renormalized ----------
template<int PN>
__device__ __forceinline__ void cubw(int o, float* w) {
    if (PN == 1) { w[0] = 1.f; return; }
    float s = __fadd_rn(__fmul_rn(__fadd_rn((float)o, 0.5f), (float)PN / 16.f), -0.5f);
    float tot = 0.f;
#pragma unroll
    for (int i = 0; i < PN; i++) {
        float x = fabsf(s - (float)i);
        float v;
        if (x >= 2.f)      v = 0.f;
        else if (x >= 1.f) v = ((-0.5f * x + 2.5f) * x - 4.f) * x + 2.f;
        else               v = ((1.5f * x - 2.5f) * x) * x + 1.f;
        w[i] = v; tot += v;
    }
#pragma unroll
    for (int i = 0; i < PN; i++) w[i] = w[i] / tot;
}

// ---------- shared up-phase (unsplit; used by k_lvl0/k_lvl1) ----------
template<int PN, int PNN>
__device__ void up_phase(int b, const int* tok_s, const float* __restrict__ emb,
                         const float* __restrict__ outPrev, float* __restrict__ outCur,
                         int isFirst, int wOff, const float* __restrict__ zrestSrc) {
    constexpr int NT = PN * PN;
    constexpr int SUB = 16 / PNN;
    __shared__ float ew[NT][33];
    __shared__ float zt[32][256];
    int tid = threadIdx.x;

    for (int idx = tid; idx < NT * 8; idx += 256) {
        int token = idx >> 3, seg = idx & 7;
        float4 v = *(const float4*)(emb + tok_s[token] * 32 + seg * 4);
        ew[token][seg*4+0] = v.x; ew[token][seg*4+1] = v.y;
        ew[token][seg*4+2] = v.z; ew[token][seg*4+3] = v.w;
    }
    __syncthreads();

    int y = tid >> 4, x = tid & 15;
    float wy[PN], wx[PN];
    cubw<PN>(y, wy);
    cubw<PN>(x, wx);
#pragma unroll
    for (int c = 0; c < 32; c++) {
        float acc = 0.f;
#pragma unroll
        for (int j = 0; j < PN; j++) {
            float tmp = 0.f;
#pragma unroll
            for (int i = 0; i < PN; i++) tmp += wx[i] * ew[j * PN + i][c];
            acc += wy[j] * tmp;
        }
        int idx = (b * 32 + c) * 256 + y * 16 + x;
        float prev = isFirst ? 0.f : outPrev[idx];
        outCur[idx] = prev + acc;
        float nz = zrestSrc[idx] - acc;
        g_zrest[idx] = nz;
        zt[c][tid] = nz;
    }
    __syncthreads();

    if (tid < PNN * PNN) {
        int ty2 = tid / PNN, tx2 = tid % PNN;
        float buf[32];
        float zqacc = 0.f;
#pragma unroll
        for (int c = 0; c < 32; c++) {
            float s = 0.f;
            for (int dy = 0; dy < SUB; dy++)
                for (int dx = 0; dx < SUB; dx++)
                    s = __fadd_rn(s, zt[c][(ty2 * SUB + dy) * 16 + tx2 * SUB + dx]);
            float zd = __fmul_rn(s, 1.f / (float)(SUB * SUB));
            buf[c] = zd;
            zqacc = __fadd_rn(zqacc, __fmul_rn(zd, zd));
        }
        int row = wOff + b * PNN * PNN + tid;
        float* dst = g_zflat + (size_t)row * 32;
#pragma unroll
        for (int s8 = 0; s8 < 8; s8++)
            *(float4*)(dst + s8 * 4) = make_float4(buf[s8*4], buf[s8*4+1],
                                                   buf[s8*4+2], buf[s8*4+3]);
        g_zsq[row] = zqacc;
    }
}

// ---------- level 0: downsample + wsq + dist + up + L1 prep ----------
__global__ void __launch_bounds__(256) k_lvl0(const float* __restrict__ z,
                                              const float* __restrict__ emb,
                                              float* __restrict__ out0) {
    __shared__ float zds[32];
    __shared__ float zqs;
    __shared__ float pdw[8];
    __shared__ int   piw[8];
    __shared__ int   tok_s[1];
    int b = blockIdx.x, tid = threadIdx.x;
    int wid = tid >> 5, lane = tid & 31;

    if (tid < 32) {
        const float* base = z + (b * 32 + tid) * 256;
        float s = 0.f;
        for (int i = 0; i < 256; i++) s = __fadd_rn(s, base[i]);
        float zd = __fmul_rn(s, 1.f / 256.f);
        zds[tid] = zd;
        float q = __fmul_rn(zd, zd);
#pragma unroll
        for (int off = 16; off; off >>= 1)
            q = __fadd_rn(q, __shfl_xor_sync(0xffffffffu, q, off));
        if (tid == 0) zqs = q;
    }
    __syncthreads();

    float zr[32];
#pragma unroll
    for (int c = 0; c < 32; c++) zr[c] = zds[c];
    float zq = zqs;

    float bd = POSINF; int bk = 0;
    for (int kk = 0; kk < 16; kk++) {
        int k = tid * 16 + kk;
        const float4* e4 = (const float4*)(emb + k * 32);
        float ws = 0.f, dot = 0.f;
#pragma unroll
        for (int s8 = 0; s8 < 8; s8++) {
            float4 w4 = e4[s8];
            ws = __fadd_rn(ws, __fmul_rn(w4.x, w4.x)); dot = __fmaf_rn(zr[s8*4+0], w4.x, dot);
            ws = __fadd_rn(ws, __fmul_rn(w4.y, w4.y)); dot = __fmaf_rn(zr[s8*4+1], w4.y, dot);
            ws = __fadd_rn(ws, __fmul_rn(w4.z, w4.z)); dot = __fmaf_rn(zr[s8*4+2], w4.z, dot);
            ws = __fadd_rn(ws, __fmul_rn(w4.w, w4.w)); dot = __fmaf_rn(zr[s8*4+3], w4.w, dot);
        }
        if (b == 0) g_wsq[k] = ws;
        float d = __fadd_rn(__fadd_rn(zq, ws), __fmul_rn(-2.f, dot));
        if (d < bd) { bd = d; bk = k; }
    }
#pragma unroll
    for (int off = 16; off; off >>= 1) {
        float od = __shfl_xor_sync(0xffffffffu, bd, off);
        int   ok = __shfl_xor_sync(0xffffffffu, bk, off);
        if (od < bd || (od == bd && ok < bk)) { bd = od; bk = ok; }
    }
    if (lane == 0) { pdw[wid] = bd; piw[wid] = bk; }
    __syncthreads();
    if (tid == 0) {
        float bdv = pdw[0]; int bkv = piw[0];
        for (int wd = 1; wd < 8; wd++)
            if (pdw[wd] < bdv || (pdw[wd] == bdv && piw[wd] < bkv)) { bdv = pdw[wd]; bkv = piw[wd]; }
        tok_s[0] = bkv;
    }
    __syncthreads();

    up_phase<1, 2>(b, tok_s, emb, out0, out0, 1, OFF1, z);
}

// ---------- level 1: dist (4 tokens) + up + L2 prep ----------
__global__ void __launch_bounds__(256) k_lvl1(const float* __restrict__ emb,
                                              const float* __restrict__ out0,
                                              float* __restrict__ out1) {
    __shared__ float zsm[4][32];
    __shared__ float zqsm[4];
    __shared__ float pdw[8][4];
    __shared__ int   piw[8][4];
    __shared__ int   tok_s[4];
    int b = blockIdx.x, tid = threadIdx.x;
    int wid = tid >> 5, lane = tid & 31;

    if (tid < 128)
        zsm[tid >> 5][tid & 31] = g_zflat[(size_t)(OFF1 + b * 4 + (tid >> 5)) * 32 + (tid & 31)];
    if (tid < 4) zqsm[tid] = g_zsq[OFF1 + b * 4 + tid];
    __syncthreads();

    int t = tid & 3, g = tid >> 2;
    float zr[32];
#pragma unroll
    for (int c = 0; c < 32; c++) zr[c] = zsm[t][c];
    float zq = zqsm[t];

    float bd = POSINF; int bk = 0;
    for (int kk = 0; kk < 64; kk++) {
        int k = g * 64 + kk;
        const float4* e4 = (const float4*)(emb + k * 32);
        float dot = 0.f;
#pragma unroll
        for (int s8 = 0; s8 < 8; s8++) {
            float4 w4 = e4[s8];
            dot = __fmaf_rn(zr[s8*4+0], w4.x, dot);
            dot = __fmaf_rn(zr[s8*4+1], w4.y, dot);
            dot = __fmaf_rn(zr[s8*4+2], w4.z, dot);
            dot = __fmaf_rn(zr[s8*4+3], w4.w, dot);
        }
        float d = __fadd_rn(__fadd_rn(zq, g_wsq[k]), __fmul_rn(-2.f, dot));
        if (d < bd) { bd = d; bk = k; }
    }
#pragma unroll
    for (int off = 4; off <= 16; off <<= 1) {
        float od = __shfl_xor_sync(0xffffffffu, bd, off);
        int   ok = __shfl_xor_sync(0xffffffffu, bk, off);
        if (od < bd || (od == bd && ok < bk)) { bd = od; bk = ok; }
    }
    if (lane < 4) { pdw[wid][lane] = bd; piw[wid][lane] = bk; }
    __syncthreads();
    if (tid < 4) {
        float bdv = pdw[0][tid]; int bkv = piw[0][tid];
        for (int wd = 1; wd < 8; wd++)
            if (pdw[wd][tid] < bdv || (pdw[wd][tid] == bdv && piw[wd][tid] < bkv))
                { bdv = pdw[wd][tid]; bkv = piw[wd][tid]; }
        tok_s[tid] = bkv;
    }
    __syncthreads();

    up_phase<2, 4>(b, tok_s, emb, out0, out1, 0, OFF2, g_zrest);
}

// ---------- dist+argmin engine (unchanged): 64 tok x 128 codes ----------
__global__ void __launch_bounds__(128) k_dist(const float* __restrict__ emb,
                                              int codesPerSplit, int iters, int rowOff) {
    __shared__ float zs[32][64];
    __shared__ float es[32][128];
    __shared__ float ws[128];
    int tid = threadIdx.x;
    int tx = tid & 15, ty = tid >> 4;
    int tb = blockIdx.x * 64;

    for (int s = tid; s < 256; s += 128) {
        int tok = s >> 2, part = s & 3;
        const float4* p = (const float4*)(g_zflat + (size_t)(rowOff + tb + tok) * 32 + part * 8);
        float4 a = p[0], b4 = p[1];
        int c0 = part * 8;
        zs[c0+0][tok]=a.x;  zs[c0+1][tok]=a.y;  zs[c0+2][tok]=a.z;  zs[c0+3][tok]=a.w;
        zs[c0+4][tok]=b4.x; zs[c0+5][tok]=b4.y; zs[c0+6][tok]=b4.z; zs[c0+7][tok]=b4.w;
    }
    float zq[8];
#pragma unroll
    for (int j = 0; j < 8; j++) zq[j] = g_zsq[rowOff + tb + ty * 8 + j];

    float bd[8]; int bk[8];
#pragma unroll
    for (int j = 0; j < 8; j++) { bd[j] = POSINF; bk[j] = 0; }

    int kbase = blockIdx.y * codesPerSplit;
    for (int it = 0; it < iters; it++) {
        int kb = kbase + it * 128;
        __syncthreads();
        for (int s = tid; s < 512; s += 128) {
            int code = s >> 2, part = s & 3;
            const float4* p = (const float4*)(emb + (kb + code) * 32 + part * 8);
            float4 a = p[0], b4 = p[1];
            int c0 = part * 8;
            es[c0+0][code]=a.x;  es[c0+1][code]=a.y;  es[c0+2][code]=a.z;  es[c0+3][code]=a.w;
            es[c0+4][code]=b4.x; es[c0+5][code]=b4.y; es[c0+6][code]=b4.z; es[c0+7][code]=b4.w;
        }
        ws[tid] = g_wsq[kb + tid];
        __syncthreads();

        ull acc[4][8];
#pragma unroll
        for (int p = 0; p < 4; p++)
#pragma unroll
            for (int k = 0; k < 8; k++) acc[p][k] = 0ull;

#pragma unroll 8
        for (int c = 0; c < 32; c++) {
            ulonglong2 za = *(const ulonglong2*)&zs[c][ty * 8];
            ulonglong2 zb = *(const ulonglong2*)&zs[c][ty * 8 + 4];
            ull zp[4] = {za.x, za.y, zb.x, zb.y};
            float4 e0 = *(const float4*)&es[c][tx * 8];
            float4 e1 = *(const float4*)&es[c][tx * 8 + 4];
            ull ed[8];
            asm("mov.b64 %0, {%1, %1};" : "=l"(ed[0]) : "f"(e0.x));
            asm("mov.b64 %0, {%1, %1};" : "=l"(ed[1]) : "f"(e0.y));
            asm("mov.b64 %0, {%1, %1};" : "=l"(ed[2]) : "f"(e0.z));
            asm("mov.b64 %0, {%1, %1};" : "=l"(ed[3]) : "f"(e0.w));
            asm("mov.b64 %0, {%1, %1};" : "=l"(ed[4]) : "f"(e1.x));
            asm("mov.b64 %0, {%1, %1};" : "=l"(ed[5]) : "f"(e1.y));
            asm("mov.b64 %0, {%1, %1};" : "=l"(ed[6]) : "f"(e1.z));
            asm("mov.b64 %0, {%1, %1};" : "=l"(ed[7]) : "f"(e1.w));
#pragma unroll
            for (int p = 0; p < 4; p++)
#pragma unroll
                for (int k = 0; k < 8; k++)
                    asm("fma.rn.f32x2 %0, %1, %2, %0;"
                        : "+l"(acc[p][k]) : "l"(zp[p]), "l"(ed[k]));
        }

#pragma unroll
        for (int p = 0; p < 4; p++) {
#pragma unroll
            for (int k = 0; k < 8; k++) {
                float lo, hi;
                asm("mov.b64 {%0, %1}, %2;" : "=f"(lo), "=f"(hi) : "l"(acc[p][k]));
                int kk = kb + tx * 8 + k;
                float wv = ws[tx * 8 + k];
                float d0 = __fadd_rn(__fadd_rn(zq[2*p],   wv), __fmul_rn(-2.f, lo));
                float d1 = __fadd_rn(__fadd_rn(zq[2*p+1], wv), __fmul_rn(-2.f, hi));
                if (d0 < bd[2*p])   { bd[2*p]   = d0; bk[2*p]   = kk; }
                if (d1 < bd[2*p+1]) { bd[2*p+1] = d1; bk[2*p+1] = kk; }
            }
        }
    }

#pragma unroll
    for (int j = 0; j < 8; j++) {
        float d = bd[j]; int k = bk[j];
#pragma unroll
        for (int off = 8; off; off >>= 1) {
            float od = __shfl_xor_sync(0xffffffffu, d, off, 16);
            int   ok = __shfl_xor_sync(0xffffffffu, k, off, 16);
            if (od < d || (od == d && ok < k)) { d = od; k = ok; }
        }
        if (tx == 0) {
            int t = tb + ty * 8 + j;
            g_pd[t * gridDim.y + blockIdx.y] = d;
            g_pi[t * gridDim.y + blockIdx.y] = k;
        }
    }
}

// ---------- quadrant-split up: reduce + gather + bicubic + zrest + prep -----
// grid (64 batches, 4 row-quadrants); 256 thr = 64 pixels x 4 channel-groups.
// Requires SUB = 16/PNN <= 4 (true for L2->L3 and L3->L4).
template<int PN, int PNN>
__global__ void __launch_bounds__(256) k_up_q(const float* __restrict__ emb,
                                              const float* __restrict__ outPrev,
                                              float* __restrict__ outCur,
                                              int KS, int wOff) {
    constexpr int NT = PN * PN;
    constexpr int SUB = 16 / PNN;
    constexpr int TROWS = 4 / SUB;         // token rows per quadrant
    constexpr int NTQ = TROWS * PNN;       // tokens per quadrant
    __shared__ float pdp[512];
    __shared__ int   pip[512];
    __shared__ int   tok_s[NT];
    __shared__ float ew[NT][33];
    __shared__ float zt[32][64];
    int b = blockIdx.x, q = blockIdx.y, tid = threadIdx.x;

    // Phase A: K-split reduce (duplicated per quadrant)
    int tot = NT * KS;
    for (int i = tid; i < tot; i += 256) {
        pdp[i] = g_pd[b * tot + i];
        pip[i] = g_pi[b * tot + i];
    }
    __syncthreads();
    if (tid < NT) {
        float bdv = pdp[tid * KS]; int bkv = pip[tid * KS];
        for (int s = 1; s < KS; s++) {
            float d = pdp[tid * KS + s]; int k = pip[tid * KS + s];
            if (d < bdv || (d == bdv && k < bkv)) { bdv = d; bkv = k; }
        }
        tok_s[tid] = bkv;
    }
    __syncthreads();

    // Phase B: gather embeddings
    for (int idx = tid; idx < NT * 8; idx += 256) {
        int token = idx >> 3, seg = idx & 7;
        float4 v = *(const float4*)(emb + tok_s[token] * 32 + seg * 4);
        ew[token][seg*4+0] = v.x; ew[token][seg*4+1] = v.y;
        ew[token][seg*4+2] = v.z; ew[token][seg*4+3] = v.w;
    }
    __syncthreads();

    // Phase C: bicubic up + out + zrest (8 channels per thread, 64 pixels)
    int pix = tid & 63, cg = tid >> 6;
    int row = (q << 2) + (pix >> 4), x = pix & 15;
    float wy[PN], wx[PN];
    cubw<PN>(row, wy);
    cubw<PN>(x, wx);
#pragma unroll
    for (int cc = 0; cc < 8; cc++) {
        int c = cg * 8 + cc;
        float acc = 0.f;
#pragma unroll
        for (int j = 0; j < PN; j++) {
            float tmp = 0.f;
#pragma unroll
            for (int i = 0; i < PN; i++) tmp += wx[i] * ew[j * PN + i][c];
            acc += wy[j] * tmp;
        }
        int idx = (b * 32 + c) * 256 + row * 16 + x;
        outCur[idx] = outPrev[idx] + acc;
        float nz = g_zrest[idx] - acc;
        g_zrest[idx] = nz;
        zt[c][pix] = nz;
    }
    __syncthreads();

    // Phase D: downsample this quadrant's tokens -> next-level zflat/zsq
    if (tid < NTQ) {
        int lty = tid / PNN, tx2 = tid % PNN;
        float buf[32];
        float zqacc = 0.f;
#pragma unroll
        for (int c = 0; c < 32; c++) {
            float s = 0.f;
            for (int dy = 0; dy < SUB; dy++)
                for (int dx = 0; dx < SUB; dx++)
                    s = __fadd_rn(s, zt[c][(lty * SUB + dy) * 16 + tx2 * SUB + dx]);
            float zd = __fmul_rn(s, 1.f / (float)(SUB * SUB));
            buf[c] = zd;
            zqacc = __fadd_rn(zqacc, __fmul_rn(zd, zd));
        }
        int ty2 = q * TROWS + lty;
        int rowI = wOff + b * PNN * PNN + ty2 * PNN + tx2;
        float* dst = g_zflat + (size_t)rowI * 32;
#pragma unroll
        for (int s8 = 0; s8 < 8; s8++)
            *(float4*)(dst + s8 * 4) = make_float4(buf[s8*4], buf[s8*4+1],
                                                   buf[s8*4+2], buf[s8*4+3]);
        g_zsq[rowI] = zqacc;
    }
}

// ---------- last level: quadrant-split reduce + gather + accumulate ---------
__global__ void __launch_bounds__(256) k_up_last(const float* __restrict__ emb,
                                                 const float* __restrict__ outPrev,
                                                 float* __restrict__ outCur, int KS) {
    int b = blockIdx.x, tid = threadIdx.x;
    int pix = tid & 63, cg = tid >> 6;
    int r = (blockIdx.y << 2) + (pix >> 4), x = pix & 15;
    int t = b * 256 + r * 16 + x;
    float bd = g_pd[t * KS]; int bk = g_pi[t * KS];
    for (int s = 1; s < KS; s++) {
        float d = g_pd[t * KS + s]; int k = g_pi[t * KS + s];
        if (d < bd || (d == bd && k < bk)) { bd = d; bk = k; }
    }
    const float4* e4 = (const float4*)(emb + bk * 32 + cg * 8);
    float4 ea = e4[0], eb = e4[1];
    float ev[8] = {ea.x, ea.y, ea.z, ea.w, eb.x, eb.y, eb.z, eb.w};
#pragma unroll
    for (int cc = 0; cc < 8; cc++) {
        int c = cg * 8 + cc;
        int idx = (b * 32 + c) * 256 + r * 16 + x;
        outCur[idx] = outPrev[idx] + ev[cc];
    }
}

extern "C" void kernel_launch(void* const* d_in, const int* in_sizes, int n_in,
                              void* d_out, int out_size) {
    const float* z = (const float*)d_in[0];
    const float* w = (const float*)d_in[1];
    float* out = (float*)d_out;
    float* o0 = out;
    float* o1 = out + (size_t)NPIX;
    float* o2 = out + 2 * (size_t)NPIX;
    float* o3 = out + 3 * (size_t)NPIX;
    float* o4 = out + 4 * (size_t)NPIX;
    dim3 gq(64, 4);

    // L0 + L1: fully fused
    k_lvl0<<<64, 256>>>(z, w, o0);
    k_lvl1<<<64, 256>>>(w, o0, o1);

    // L2: 1024 tokens, KS=16
    k_dist<<<dim3(16, 16), 128>>>(w, 256, 2, OFF2);
    k_up_q<4, 8><<<gq, 256>>>(w, o1, o2, 16, OFF3);

    // L3: 4096 tokens, KS=8
    k_dist<<<dim3(64, 8), 128>>>(w, 512, 4, OFF3);
    k_up_q<8, 16><<<gq, 256>>>(w, o2, o3, 8, OFF4);

    // L4: 16384 tokens, KS=4
    k_dist<<<dim3(256, 4), 128>>>(w, 1024, 8, OFF4);
    k_up_last<<<gq, 256>>>(w, o3, o4, 4);
}